// round 10
// baseline (speedup 1.0000x reference)
#include <cuda_runtime.h>

// Heisenberg-picture evaluation of the 8-qubit, 2-layer circuit.
// ev = sum over 27 Pauli strings of kappa_mu * prod_w D_w[code(mu,w)].
// All Clifford (CNOT-ring) structure is resolved at compile time.
// Latency-optimized: theta in __constant__, per-warp prologue (no
// __syncthreads), x loads issued before the prologue.

#define TPB 128
#define NW (TPB / 32)

// ---------------- compile-time Pauli machinery ----------------
// mu in [0,27): slot paulis p2 = mu/9, p4 = (mu/3)%3, p6 = mu%3 ; 0=X,1=Y,2=Z.
// Returns: bits [2w,2w+1] = pauli code of wire w in ring1-conjugated string
// (0=I,1=X,2=Y,3=Z); bit 16 = sign (1 -> negative).
constexpr __host__ __device__ unsigned conj_pack(int mu) {
    int a[8] = {}, b[8] = {};
    int tph = 0;                       // initial #Y (phase i^tph in XZ rep)
    const int p[3] = { mu / 9, (mu / 3) % 3, mu % 3 };
    const int ws[3] = { 2, 4, 6 };
    for (int i = 0; i < 3; i++) {
        int q = p[i], w = ws[i];
        if (q == 0)      { a[w] = 1; }                  // X
        else if (q == 1) { a[w] = 1; b[w] = 1; tph++; } // Y = i X Z
        else             { b[w] = 1; }                  // Z
    }
    // Ring1 (r=1): state-order gates w=0..7, conjugate outermost-first g=7..0.
    // CNOT(c,t): X_c->X_cX_t, Z_t->Z_cZ_t (no reorder signs in XZ rep).
    for (int g = 7; g >= 0; g--) {
        int c = g, t = (g + 1) & 7;
        a[t] ^= a[c];
        b[c] ^= b[t];
    }
    unsigned pack = 0; int ny = 0;
    for (int w = 0; w < 8; w++) {
        int code = a[w] ? (b[w] ? 2 : 1) : (b[w] ? 3 : 0);
        if (code == 2) ny++;
        pack |= (unsigned)code << (2 * w);
    }
    int sg = ((tph - ny) % 4 + 4) % 4;     // 0 or 2 for a Hermitian result
    if (sg == 2) pack |= (1u << 16);
    return pack;
}

// constant-bank copy (for the kappa sign at runtime)
__constant__ unsigned c_pk[27] = {
    conj_pack(0),  conj_pack(1),  conj_pack(2),  conj_pack(3),  conj_pack(4),
    conj_pack(5),  conj_pack(6),  conj_pack(7),  conj_pack(8),  conj_pack(9),
    conj_pack(10), conj_pack(11), conj_pack(12), conj_pack(13), conj_pack(14),
    conj_pack(15), conj_pack(16), conj_pack(17), conj_pack(18), conj_pack(19),
    conj_pack(20), conj_pack(21), conj_pack(22), conj_pack(23), conj_pack(24),
    conj_pack(25), conj_pack(26)
};

// theta (48 floats), copied in at launch via async D2D memcpy-to-symbol
__constant__ float c_theta[48];

// ---- string product, fully unrolled, compile-time register indexing ----
template<unsigned PKC, int W, bool HAVE>
__device__ __forceinline__ float sprod(const float (&D)[8][3], float t) {
    if constexpr (W == 8) {
        return t;
    } else {
        constexpr int c = (PKC >> (2 * W)) & 3;
        if constexpr (c == 0) {
            return sprod<PKC, W + 1, HAVE>(D, t);
        } else if constexpr (HAVE) {
            return sprod<PKC, W + 1, true>(D, t * D[W][c - 1]);
        } else {
            return sprod<PKC, W + 1, true>(D, D[W][c - 1]);
        }
    }
}

template<int MU>
__device__ __forceinline__ void accall(float (&ev)[4], const float* kap,
                                       const float (&D)[8][3]) {
    if constexpr (MU < 27) {
        constexpr unsigned pk = conj_pack(MU);
        static_assert((pk & 0xFFFFu) != 0, "string must be non-identity");
        constexpr unsigned pkc = pk & 0xFFFFu;  // sign folded into kap
        float p = sprod<pkc, 0, false>(D, 0.f);
        ev[MU & 3] = fmaf(kap[MU], p, ev[MU & 3]);
        accall<MU + 1>(ev, kap, D);
    }
}

// ---------------- kernel ----------------
__global__ __launch_bounds__(TPB)
void qev_kernel(const float* __restrict__ x, float* __restrict__ out, int B)
{
    // Rot SO(3) rows (only Y/Z columns needed: <X>=0):
    //   O[X] = ( . , -cw*ct*sp - sw*cp , cw*st )
    //   O[Y] = ( . , -sw*ct*sp + cw*cp , sw*st )
    //   O[Z] = ( . ,  st*sp            , ct    )
    __shared__ float sEs[NW][8][6];   // [warp][wire][{Xy,Xz,Yy,Yz,Zy,Zz}]
    __shared__ float sZr[NW][3][4];   // layer-2 Z-rows, wires {2,4,6} (pad 4)
    __shared__ float sKap[NW][28];

    const int tid  = threadIdx.x;
    const int warp = tid >> 5;
    const int lane = tid & 31;
    const int e = blockIdx.x * TPB + tid;

    // ---- issue x loads FIRST; latency overlaps the prologue below ----
    float4 xa = make_float4(0.f, 0.f, 0.f, 0.f), xb = xa;
    const bool valid = (e < B);
    if (valid) {
        xa = *(const float4*)(x + (size_t)e * 8);
        xb = *(const float4*)(x + (size_t)e * 8 + 4);
    }

    // ---- per-warp prologue from constant theta (no cross-warp sync) ----
    if (lane < 8) {
        const float* t = c_theta + lane * 3;            // layer 0, wire=lane
        float sp, cp, st, ct, sw, cw;
        __sincosf(t[0], &sp, &cp);
        __sincosf(t[1], &st, &ct);
        __sincosf(t[2], &sw, &cw);
        sEs[warp][lane][0] = -cw * ct * sp - sw * cp;  sEs[warp][lane][1] = cw * st;
        sEs[warp][lane][2] = -sw * ct * sp + cw * cp;  sEs[warp][lane][3] = sw * st;
        sEs[warp][lane][4] =  st * sp;                 sEs[warp][lane][5] = ct;
    } else if (lane >= 29) {
        const int i = lane - 29;                        // 0,1,2 -> wires 2,4,6
        const float* t = c_theta + 24 + (2 + 2 * i) * 3; // layer 1
        float sp, cp, st, ct;
        __sincosf(t[0], &sp, &cp);
        __sincosf(t[1], &st, &ct);
        sZr[warp][i][0] = -st * cp;
        sZr[warp][i][1] =  st * sp;
        sZr[warp][i][2] =  ct;
    }
    __syncwarp();
    if (lane < 27) {
        float k = sZr[warp][0][lane / 9] * sZr[warp][1][(lane / 3) % 3]
                * sZr[warp][2][lane % 3];
        if (c_pk[lane] >> 16) k = -k;
        sKap[warp][lane] = k;
    }
    __syncwarp();
    if (!valid) return;

    const float xs[8] = { xa.x, xa.y, xa.z, xa.w, xb.x, xb.y, xb.z, xb.w };

    float D[8][3];
#pragma unroll
    for (int w = 0; w < 8; w++) {
        float s, c;
        __sincosf(xs[w], &s, &c);     // Bloch: <Y>=-sin x, <Z>=cos x
        float ny = -s;
#pragma unroll
        for (int p = 0; p < 3; p++)
            D[w][p] = fmaf(sEs[warp][w][2 * p], ny, sEs[warp][w][2 * p + 1] * c);
    }

    float ev[4] = { 0.f, 0.f, 0.f, 0.f };
    accall<0>(ev, sKap[warp], D);
    float e01 = ev[0] + ev[1], e23 = ev[2] + ev[3];

    out[e] = fmaf(0.5f, e01 + e23, 0.5f);
}

extern "C" void kernel_launch(void* const* d_in, const int* in_sizes, int n_in,
                              void* d_out, int out_size)
{
    const float* x     = (const float*)d_in[0];
    const float* theta = (const float*)d_in[1];
    if (n_in >= 2 && in_sizes[0] == 48) {   // defensive input-order swap
        const float* tmp = x; x = theta; theta = tmp;
    }
    // async D2D copy into constant bank (graph-capturable memcpy node)
    cudaMemcpyToSymbolAsync(c_theta, theta, 48 * sizeof(float), 0,
                            cudaMemcpyDeviceToDevice);
    int B = out_size;
    int blocks = (B + TPB - 1) / TPB;
    qev_kernel<<<blocks, TPB>>>(x, (float*)d_out, B);
}

// round 12
// speedup vs baseline: 1.5507x; 1.5507x over previous
#include <cuda_runtime.h>

// Heisenberg-picture evaluation of the 8-qubit, 2-layer circuit.
// ev = sum over 27 Pauli strings of kappa_mu * prod_w D_w[code(mu,w)].
// All Clifford (CNOT-ring) structure is resolved at compile time.
// 2 elements per thread for ILP; theta read directly (48 floats, L2-hot).

#define TPB 128
#define EPT 2                 // elements per thread

// ---------------- compile-time Pauli machinery ----------------
// mu in [0,27): slot paulis p2 = mu/9, p4 = (mu/3)%3, p6 = mu%3 ; 0=X,1=Y,2=Z.
// Returns: bits [2w,2w+1] = pauli code of wire w in ring1-conjugated string
// (0=I,1=X,2=Y,3=Z); bit 16 = sign (1 -> negative).
constexpr __host__ __device__ unsigned conj_pack(int mu) {
    int a[8] = {}, b[8] = {};
    int tph = 0;                       // initial #Y (phase i^tph in XZ rep)
    const int p[3] = { mu / 9, (mu / 3) % 3, mu % 3 };
    const int ws[3] = { 2, 4, 6 };
    for (int i = 0; i < 3; i++) {
        int q = p[i], w = ws[i];
        if (q == 0)      { a[w] = 1; }                  // X
        else if (q == 1) { a[w] = 1; b[w] = 1; tph++; } // Y = i X Z
        else             { b[w] = 1; }                  // Z
    }
    // Ring1 (r=1): state-order gates w=0..7, conjugate outermost-first g=7..0.
    // CNOT(c,t): X_c->X_cX_t, Z_t->Z_cZ_t (no reorder signs in XZ rep).
    for (int g = 7; g >= 0; g--) {
        int c = g, t = (g + 1) & 7;
        a[t] ^= a[c];
        b[c] ^= b[t];
    }
    unsigned pack = 0; int ny = 0;
    for (int w = 0; w < 8; w++) {
        int code = a[w] ? (b[w] ? 2 : 1) : (b[w] ? 3 : 0);
        if (code == 2) ny++;
        pack |= (unsigned)code << (2 * w);
    }
    int sg = ((tph - ny) % 4 + 4) % 4;     // 0 or 2 for a Hermitian result
    if (sg == 2) pack |= (1u << 16);
    return pack;
}

// constant-bank copy (for the kappa sign at runtime)
__constant__ unsigned c_pk[27] = {
    conj_pack(0),  conj_pack(1),  conj_pack(2),  conj_pack(3),  conj_pack(4),
    conj_pack(5),  conj_pack(6),  conj_pack(7),  conj_pack(8),  conj_pack(9),
    conj_pack(10), conj_pack(11), conj_pack(12), conj_pack(13), conj_pack(14),
    conj_pack(15), conj_pack(16), conj_pack(17), conj_pack(18), conj_pack(19),
    conj_pack(20), conj_pack(21), conj_pack(22), conj_pack(23), conj_pack(24),
    conj_pack(25), conj_pack(26)
};

// ---- string product, fully unrolled, compile-time register indexing ----
template<unsigned PKC, int W, bool HAVE>
__device__ __forceinline__ float sprod(const float (&D)[8][3], float t) {
    if constexpr (W == 8) {
        return t;
    } else {
        constexpr int c = (PKC >> (2 * W)) & 3;
        if constexpr (c == 0) {
            return sprod<PKC, W + 1, HAVE>(D, t);
        } else if constexpr (HAVE) {
            return sprod<PKC, W + 1, true>(D, t * D[W][c - 1]);
        } else {
            return sprod<PKC, W + 1, true>(D, D[W][c - 1]);
        }
    }
}

// Accumulate all 27 strings for TWO elements, interleaved for ILP.
template<int MU>
__device__ __forceinline__ void accall2(float (&ev0)[2], float (&ev1)[2],
                                        const float* kap,
                                        const float (&D0)[8][3],
                                        const float (&D1)[8][3]) {
    if constexpr (MU < 27) {
        constexpr unsigned pk = conj_pack(MU);
        static_assert((pk & 0xFFFFu) != 0, "string must be non-identity");
        constexpr unsigned pkc = pk & 0xFFFFu;  // sign folded into kap
        float k = kap[MU];
        float p0 = sprod<pkc, 0, false>(D0, 0.f);
        float p1 = sprod<pkc, 0, false>(D1, 0.f);
        ev0[MU & 1] = fmaf(k, p0, ev0[MU & 1]);
        ev1[MU & 1] = fmaf(k, p1, ev1[MU & 1]);
        accall2<MU + 1>(ev0, ev1, kap, D0, D1);
    }
}

// ---------------- kernel ----------------
__global__ __launch_bounds__(TPB)
void qev_kernel(const float* __restrict__ x, const float* __restrict__ theta,
                float* __restrict__ out, int B)
{
    // Rot SO(3) rows (only Y/Z columns needed: <X>=0):
    //   O[X] = ( . , -cw*ct*sp - sw*cp , cw*st )
    //   O[Y] = ( . , -sw*ct*sp + cw*cp , sw*st )
    //   O[Z] = ( . ,  st*sp            , ct    )
    __shared__ float Es[8][3][2];  // [wire][pauli X/Y/Z][Ycoef, Zcoef]
    __shared__ float zr[3][3];     // layer-2 Z-rows, wires {2,4,6} x {X,Y,Z}
    __shared__ float kap[27];      // holds kappa/2 (output scale folded in)

    const int tid = threadIdx.x;
    if (tid < 8) {
        const float* t = theta + tid * 3;            // layer 0
        float sp, cp, st, ct, sw, cw;
        __sincosf(t[0], &sp, &cp);
        __sincosf(t[1], &st, &ct);
        __sincosf(t[2], &sw, &cw);
        Es[tid][0][0] = -cw * ct * sp - sw * cp;  Es[tid][0][1] = cw * st;
        Es[tid][1][0] = -sw * ct * sp + cw * cp;  Es[tid][1][1] = sw * st;
        Es[tid][2][0] =  st * sp;                 Es[tid][2][1] = ct;
    } else if (tid >= 32 && tid < 35) {
        int i = tid - 32;
        const float* t = theta + 24 + (2 + 2 * i) * 3;  // layer 1, wire 2/4/6
        float sp, cp, st, ct;
        __sincosf(t[0], &sp, &cp);
        __sincosf(t[1], &st, &ct);
        zr[i][0] = -st * cp;
        zr[i][1] =  st * sp;
        zr[i][2] =  ct;
    }
    __syncthreads();
    if (tid < 27) {
        float k = 0.5f * zr[0][tid / 9] * zr[1][(tid / 3) % 3] * zr[2][tid % 3];
        if (c_pk[tid] >> 16) k = -k;
        kap[tid] = k;
    }

    // issue both elements' x loads while the last barrier settles
    const int e0 = blockIdx.x * (TPB * EPT) + tid;
    const int e1 = e0 + TPB;
    float4 a0 = make_float4(0.f,0.f,0.f,0.f), b0 = a0, a1 = a0, b1 = a0;
    const bool v0 = (e0 < B), v1 = (e1 < B);
    if (v0) {
        a0 = *(const float4*)(x + (size_t)e0 * 8);
        b0 = *(const float4*)(x + (size_t)e0 * 8 + 4);
    }
    if (v1) {
        a1 = *(const float4*)(x + (size_t)e1 * 8);
        b1 = *(const float4*)(x + (size_t)e1 * 8 + 4);
    }
    __syncthreads();

    const float xs0[8] = { a0.x, a0.y, a0.z, a0.w, b0.x, b0.y, b0.z, b0.w };
    const float xs1[8] = { a1.x, a1.y, a1.z, a1.w, b1.x, b1.y, b1.z, b1.w };

    float D0[8][3], D1[8][3];
#pragma unroll
    for (int w = 0; w < 8; w++) {
        float s0, c0, s1, c1;
        __sincosf(xs0[w], &s0, &c0);   // Bloch: <Y>=-sin x, <Z>=cos x
        __sincosf(xs1[w], &s1, &c1);
        float ny0 = -s0, ny1 = -s1;
#pragma unroll
        for (int p = 0; p < 3; p++) {
            D0[w][p] = fmaf(Es[w][p][0], ny0, Es[w][p][1] * c0);
            D1[w][p] = fmaf(Es[w][p][0], ny1, Es[w][p][1] * c1);
        }
    }

    float ev0[2] = { 0.25f, 0.25f };   // 0.5*(ev+1) with kap pre-halved
    float ev1[2] = { 0.25f, 0.25f };
    accall2<0>(ev0, ev1, kap, D0, D1);

    if (v0) out[e0] = ev0[0] + ev0[1];
    if (v1) out[e1] = ev1[0] + ev1[1];
}

extern "C" void kernel_launch(void* const* d_in, const int* in_sizes, int n_in,
                              void* d_out, int out_size)
{
    const float* x     = (const float*)d_in[0];
    const float* theta = (const float*)d_in[1];
    if (n_in >= 2 && in_sizes[0] == 48) {   // defensive input-order swap
        const float* tmp = x; x = theta; theta = tmp;
    }
    int B = out_size;
    int blocks = (B + TPB * EPT - 1) / (TPB * EPT);
    qev_kernel<<<blocks, TPB>>>(x, theta, (float*)d_out, B);
}

// round 14
// speedup vs baseline: 1.6294x; 1.0508x over previous
#include <cuda_runtime.h>

// Heisenberg-picture evaluation of the 8-qubit, 2-layer circuit.
// ev = sum over 27 Pauli strings of kappa_mu * prod_w D_w[code(mu,w)].
// Clifford structure resolved at compile time; 2 elements per thread
// evaluated in PACKED f32x2 (FFMA2/FMUL2) lanes.

#define TPB 128
#define EPT 2

typedef unsigned long long u64;

// ---------------- packed f32x2 helpers (sm_103a) ----------------
__device__ __forceinline__ u64 pk2(float lo, float hi) {
    u64 r; asm("mov.b64 %0,{%1,%2};" : "=l"(r) : "f"(lo), "f"(hi)); return r;
}
__device__ __forceinline__ void up2(float& lo, float& hi, u64 a) {
    asm("mov.b64 {%0,%1},%2;" : "=f"(lo), "=f"(hi) : "l"(a));
}
__device__ __forceinline__ u64 mul2(u64 a, u64 b) {
    u64 r; asm("mul.rn.f32x2 %0,%1,%2;" : "=l"(r) : "l"(a), "l"(b)); return r;
}
__device__ __forceinline__ u64 add2(u64 a, u64 b) {
    u64 r; asm("add.rn.f32x2 %0,%1,%2;" : "=l"(r) : "l"(a), "l"(b)); return r;
}
__device__ __forceinline__ u64 fma2(u64 a, u64 b, u64 c) {
    u64 r; asm("fma.rn.f32x2 %0,%1,%2,%3;" : "=l"(r) : "l"(a), "l"(b), "l"(c)); return r;
}

// ---------------- compile-time Pauli machinery ----------------
// mu in [0,27): slot paulis p2 = mu/9, p4 = (mu/3)%3, p6 = mu%3 ; 0=X,1=Y,2=Z.
// Returns: bits [2w,2w+1] = pauli code of wire w in ring1-conjugated string
// (0=I,1=X,2=Y,3=Z); bit 16 = sign (1 -> negative).
constexpr __host__ __device__ unsigned conj_pack(int mu) {
    int a[8] = {}, b[8] = {};
    int tph = 0;                       // initial #Y (phase i^tph in XZ rep)
    const int p[3] = { mu / 9, (mu / 3) % 3, mu % 3 };
    const int ws[3] = { 2, 4, 6 };
    for (int i = 0; i < 3; i++) {
        int q = p[i], w = ws[i];
        if (q == 0)      { a[w] = 1; }                  // X
        else if (q == 1) { a[w] = 1; b[w] = 1; tph++; } // Y = i X Z
        else             { b[w] = 1; }                  // Z
    }
    // Ring1 (r=1): conjugate gates g=7..0.  CNOT(c,t): X_c->X_cX_t, Z_t->Z_cZ_t.
    for (int g = 7; g >= 0; g--) {
        int c = g, t = (g + 1) & 7;
        a[t] ^= a[c];
        b[c] ^= b[t];
    }
    unsigned pack = 0; int ny = 0;
    for (int w = 0; w < 8; w++) {
        int code = a[w] ? (b[w] ? 2 : 1) : (b[w] ? 3 : 0);
        if (code == 2) ny++;
        pack |= (unsigned)code << (2 * w);
    }
    int sg = ((tph - ny) % 4 + 4) % 4;     // 0 or 2 for a Hermitian result
    if (sg == 2) pack |= (1u << 16);
    return pack;
}

// constant-bank copy (for the kappa sign at runtime)
__constant__ unsigned c_pk[27] = {
    conj_pack(0),  conj_pack(1),  conj_pack(2),  conj_pack(3),  conj_pack(4),
    conj_pack(5),  conj_pack(6),  conj_pack(7),  conj_pack(8),  conj_pack(9),
    conj_pack(10), conj_pack(11), conj_pack(12), conj_pack(13), conj_pack(14),
    conj_pack(15), conj_pack(16), conj_pack(17), conj_pack(18), conj_pack(19),
    conj_pack(20), conj_pack(21), conj_pack(22), conj_pack(23), conj_pack(24),
    conj_pack(25), conj_pack(26)
};

// ---- packed string product, fully unrolled, compile-time indexing ----
template<unsigned PKC, int W, bool HAVE>
__device__ __forceinline__ u64 sprod2(const u64 (&D)[8][3], u64 t) {
    if constexpr (W == 8) {
        return t;
    } else {
        constexpr int c = (PKC >> (2 * W)) & 3;
        if constexpr (c == 0) {
            return sprod2<PKC, W + 1, HAVE>(D, t);
        } else if constexpr (HAVE) {
            return sprod2<PKC, W + 1, true>(D, mul2(t, D[W][c - 1]));
        } else {
            return sprod2<PKC, W + 1, true>(D, D[W][c - 1]);
        }
    }
}

template<int MU>
__device__ __forceinline__ void accall2(u64 (&ev)[4], const u64* kap2,
                                        const u64 (&D)[8][3]) {
    if constexpr (MU < 27) {
        constexpr unsigned pk = conj_pack(MU);
        static_assert((pk & 0xFFFFu) != 0, "string must be non-identity");
        constexpr unsigned pkc = pk & 0xFFFFu;  // sign folded into kappa
        u64 p = sprod2<pkc, 0, false>(D, 0ull);
        ev[MU & 3] = fma2(kap2[MU], p, ev[MU & 3]);
        accall2<MU + 1>(ev, kap2, D);
    }
}

// ---------------- kernel ----------------
__global__ __launch_bounds__(TPB)
void qev_kernel(const float* __restrict__ x, const float* __restrict__ theta,
                float* __restrict__ out, int B)
{
    // Rot SO(3) rows (only Y/Z columns needed: <X>=0):
    //   O[X] = ( . , -cw*ct*sp - sw*cp , cw*st )
    //   O[Y] = ( . , -sw*ct*sp + cw*cp , sw*st )
    //   O[Z] = ( . ,  st*sp            , ct    )
    __shared__ u64  Es2[8][3][2];  // [wire][pauli][{Ycoef,Zcoef}], value-duplicated pairs
    __shared__ float zr[3][3];     // layer-2 Z-rows, wires {2,4,6} x {X,Y,Z}
    __shared__ u64  kap2[27];      // (kappa/2, kappa/2) pairs

    const int tid = threadIdx.x;
    if (tid < 8) {
        const float* t = theta + tid * 3;            // layer 0
        float sp, cp, st, ct, sw, cw;
        __sincosf(t[0], &sp, &cp);
        __sincosf(t[1], &st, &ct);
        __sincosf(t[2], &sw, &cw);
        float xy = -cw * ct * sp - sw * cp, xz = cw * st;
        float yy = -sw * ct * sp + cw * cp, yz = sw * st;
        float zy =  st * sp,                zz = ct;
        Es2[tid][0][0] = pk2(xy, xy);  Es2[tid][0][1] = pk2(xz, xz);
        Es2[tid][1][0] = pk2(yy, yy);  Es2[tid][1][1] = pk2(yz, yz);
        Es2[tid][2][0] = pk2(zy, zy);  Es2[tid][2][1] = pk2(zz, zz);
    } else if (tid >= 32 && tid < 35) {
        int i = tid - 32;
        const float* t = theta + 24 + (2 + 2 * i) * 3;  // layer 1, wire 2/4/6
        float sp, cp, st, ct;
        __sincosf(t[0], &sp, &cp);
        __sincosf(t[1], &st, &ct);
        zr[i][0] = -st * cp;
        zr[i][1] =  st * sp;
        zr[i][2] =  ct;
    }
    __syncthreads();
    if (tid < 27) {
        float k = 0.5f * zr[0][tid / 9] * zr[1][(tid / 3) % 3] * zr[2][tid % 3];
        if (c_pk[tid] >> 16) k = -k;
        kap2[tid] = pk2(k, k);
    }

    // issue both elements' x loads while the last barrier settles
    const int e0 = blockIdx.x * (TPB * EPT) + tid;
    const int e1 = e0 + TPB;
    float4 a0 = make_float4(0.f,0.f,0.f,0.f), b0 = a0, a1 = a0, b1 = a0;
    const bool v0 = (e0 < B), v1 = (e1 < B);
    if (v0) {
        a0 = *(const float4*)(x + (size_t)e0 * 8);
        b0 = *(const float4*)(x + (size_t)e0 * 8 + 4);
    }
    if (v1) {
        a1 = *(const float4*)(x + (size_t)e1 * 8);
        b1 = *(const float4*)(x + (size_t)e1 * 8 + 4);
    }
    __syncthreads();

    const float xs0[8] = { a0.x, a0.y, a0.z, a0.w, b0.x, b0.y, b0.z, b0.w };
    const float xs1[8] = { a1.x, a1.y, a1.z, a1.w, b1.x, b1.y, b1.z, b1.w };

    u64 D[8][3];
#pragma unroll
    for (int w = 0; w < 8; w++) {
        float s0, c0, s1, c1;
        __sincosf(xs0[w], &s0, &c0);   // Bloch: <Y>=-sin x, <Z>=cos x
        __sincosf(xs1[w], &s1, &c1);
        u64 ny = pk2(-s0, -s1);
        u64 cc = pk2( c0,  c1);
#pragma unroll
        for (int p = 0; p < 3; p++)
            D[w][p] = fma2(Es2[w][p][0], ny, mul2(Es2[w][p][1], cc));
    }

    // result = 0.5 + 0.5*ev, kappa pre-halved -> seed total must be 0.5
    u64 ev[4] = { pk2(0.5f, 0.5f), 0ull, 0ull, 0ull };
    accall2<0>(ev, kap2, D);
    u64 r = add2(add2(ev[0], ev[1]), add2(ev[2], ev[3]));
    float r0, r1;
    up2(r0, r1, r);

    if (v0) out[e0] = r0;
    if (v1) out[e1] = r1;
}

extern "C" void kernel_launch(void* const* d_in, const int* in_sizes, int n_in,
                              void* d_out, int out_size)
{
    const float* x     = (const float*)d_in[0];
    const float* theta = (const float*)d_in[1];
    if (n_in >= 2 && in_sizes[0] == 48) {   // defensive input-order swap
        const float* tmp = x; x = theta; theta = tmp;
    }
    int B = out_size;
    int blocks = (B + TPB * EPT - 1) / (TPB * EPT);
    qev_kernel<<<blocks, TPB>>>(x, theta, (float*)d_out, B);
}